// round 8
// baseline (speedup 1.0000x reference)
#include <cuda_runtime.h>
#include <cuda_bf16.h>
#include <stdint.h>
#include <math.h>

#define BB 256     // batch
#define HH 512     // hidden
#define VV 100     // vocab
#define TT 200     // steps

// fp32 hidden-state history (proj + epilogue need fp32 h)
__device__ float g_hist[(size_t)TT * BB * HH];
// bf16 hi/lo ping-pong of previous hidden state
__device__ __nv_bfloat16 g_hh[2][BB * HH];
__device__ __nv_bfloat16 g_hl[2][BB * HH];
// packed weights: row n = jb*96 + g*16 + j  (jb=0..31, g=0..5, j=0..15), k=0..511
__device__ __nv_bfloat16 g_wh[6 * HH * HH];
__device__ __nv_bfloat16 g_wl[6 * HH * HH];
// per-block progress flags: g_flags[(bq*32 + jb)*32] = last step published
__device__ unsigned int g_flags[4 * 32 * 32];

__device__ __forceinline__ float sigmoidf_(float x) {
    return 1.0f / (1.0f + expf(-x));
}

// ---------------------------------------------------------------------------
// async / mma / sync helpers
// ---------------------------------------------------------------------------
__device__ __forceinline__ void cp_async16(void* smem_dst, const void* gmem_src) {
    unsigned int s = (unsigned int)__cvta_generic_to_shared(smem_dst);
    asm volatile("cp.async.cg.shared.global [%0], [%1], 16;\n" :: "r"(s), "l"(gmem_src));
}
#define CP_COMMIT() asm volatile("cp.async.commit_group;\n" ::: "memory")
#define CP_WAIT(n)  asm volatile("cp.async.wait_group %0;\n" :: "n"(n) : "memory")

__device__ __forceinline__ void ldsm4(uint32_t r[4], const void* p) {
    unsigned int s = (unsigned int)__cvta_generic_to_shared(p);
    asm volatile("ldmatrix.sync.aligned.m8n8.x4.shared.b16 {%0,%1,%2,%3}, [%4];"
                 : "=r"(r[0]), "=r"(r[1]), "=r"(r[2]), "=r"(r[3]) : "r"(s));
}

__device__ __forceinline__ void mma_bf16(float d[4], const uint32_t a[4],
                                         uint32_t b0, uint32_t b1) {
    asm volatile(
        "mma.sync.aligned.m16n8k16.row.col.f32.bf16.bf16.f32 "
        "{%0,%1,%2,%3}, {%4,%5,%6,%7}, {%8,%9}, {%0,%1,%2,%3};"
        : "+f"(d[0]), "+f"(d[1]), "+f"(d[2]), "+f"(d[3])
        : "r"(a[0]), "r"(a[1]), "r"(a[2]), "r"(a[3]), "r"(b0), "r"(b1));
}

__device__ __forceinline__ unsigned int ld_acq(const unsigned int* p) {
    unsigned int v;
    asm volatile("ld.acquire.gpu.u32 %0, [%1];" : "=r"(v) : "l"(p));
    return v;
}
__device__ __forceinline__ void st_rel(unsigned int* p, unsigned int v) {
    asm volatile("st.release.gpu.u32 [%0], %1;" :: "l"(p), "r"(v));
}

// ---------------------------------------------------------------------------
// One-time weight prep: pack + split fp32 -> bf16 hi/lo.
// ---------------------------------------------------------------------------
__global__ __launch_bounds__(256) void prep_weights(
    const float* __restrict__ w_ih, const float* __restrict__ w_hh)
{
    int idx = blockIdx.x * 256 + threadIdx.x;
    if (idx >= 6 * HH * HH) return;
    int n = idx / HH, k = idx % HH;
    int jb = n / 96, rr = n % 96, g = rr / 16, j = rr % 16;
    const float* src = (g < 3) ? w_ih : w_hh;
    float v = src[(size_t)((g % 3) * HH + jb * 16 + j) * HH + k];
    __nv_bfloat16 hi = __float2bfloat16(v);
    g_wh[idx] = hi;
    g_wl[idx] = __float2bfloat16(v - __bfloat162float(hi));
}

__global__ __launch_bounds__(1024) void reset_flags_kernel() {
    int i = blockIdx.x * 1024 + threadIdx.x;
    if (i < 4 * 32 * 32) g_flags[i] = 0u;
}

// ---------------------------------------------------------------------------
// Convert fp32 h -> bf16 hi/lo (after step 0)
// ---------------------------------------------------------------------------
__global__ __launch_bounds__(256) void convert_h(
    const float* __restrict__ h, __nv_bfloat16* __restrict__ hh,
    __nv_bfloat16* __restrict__ hl)
{
    int idx = blockIdx.x * 256 + threadIdx.x;
    if (idx >= BB * HH) return;
    float v = h[idx];
    __nv_bfloat16 hi = __float2bfloat16(v);
    hh[idx] = hi;
    hl[idx] = __float2bfloat16(v - __bfloat162float(hi));
}

// ---------------------------------------------------------------------------
// Persistent tensor-core GRU, v3: fine-grained dataflow sync.
// Grid (32 jb, 4 bq) = 128 blocks, 384 threads (12 warps: 4 mw x 3 nv(n=32)).
// B tile (96x512, hi+lo) XOR-swizzled, SMEM-resident whole kernel.
// A (h hi/lo) streamed per step, k=64 chunks, double buffer.
// Sync: per-block release flags; chunk c of step t waits only on its 4
// producer blocks' flags >= t-1 (no global barrier, no all-thread fence).
// ---------------------------------------------------------------------------
#define THR    384
#define B_MATS (96 * 512)                   // bf16 per B matrix (swizzled, no pad)
#define OFF_A  (2 * B_MATS)                 // 98304 bf16
#define A_MATS (64 * 64)                    // bf16 per A matrix per chunk (k=64)
#define A_BUF  (2 * A_MATS)                 // hi+lo per buffer = 8192 bf16
#define SMEM_P ((OFF_A + 2 * A_BUF) * 2)    // 229376 bytes (224 KB)
#define NCH    8                            // K chunks of 64

__global__ __launch_bounds__(THR) void gru_persistent(
    const float* __restrict__ b_ih,
    const float* __restrict__ b_hh,
    float* __restrict__ hist,                 // [TT][BB][HH]
    __nv_bfloat16* __restrict__ hh_base,      // [2][BB*HH]
    __nv_bfloat16* __restrict__ hl_base)
{
    extern __shared__ __align__(16) __nv_bfloat16 dsm[];

    const int tid  = threadIdx.x;
    const int lane = tid & 31;
    const int w    = tid >> 5;           // 0..11
    const int mw   = w & 3;              // m16 tile
    const int nv   = w >> 2;             // 0..2, n=32 each
    const int jb   = blockIdx.x;         // 0..31
    const int bq   = blockIdx.y;         // 0..3
    const int b0   = bq * 64;

    unsigned int* my_flag = &g_flags[(bq * 32 + jb) * 32];

    // ================= resident B load (swizzled, once) =================
    for (int i = tid; i < 2 * 96 * 64; i += THR) {     // 16B granules
        const int mat = i / (96 * 64);
        const int rr  = i % (96 * 64);
        const int row = rr >> 6;
        const int g   = rr & 63;
        const int gs  = (g & 56) | ((g ^ row) & 7);
        const __nv_bfloat16* src =
            (mat ? g_wl : g_wh) + (size_t)(jb * 96 + row) * HH + g * 8;
        cp_async16(dsm + mat * B_MATS + row * 512 + gs * 8, src);
    }
    CP_COMMIT();

    // ========== per-thread A-chunk cp.async descriptors (<=3 each) =========
    int aMat[3], aDst[3], aSrc[3];
    #pragma unroll
    for (int k = 0; k < 3; k++) {
        const int i = tid + THR * k;
        if (i < 1024) {
            const int mat = i >> 9;
            const int r   = (i >> 3) & 63;
            const int g   = i & 7;
            aMat[k] = mat;
            aDst[k] = mat * A_MATS + r * 64 + ((g ^ (r & 7)) * 8);
            aSrc[k] = (b0 + r) * HH + g * 8;
        }
    }
    const bool a3 = (tid + 2 * THR < 1024);

    // ================= ldmatrix lane invariants =================
    const int a_row  = mw * 16 + (lane & 15);
    const int a_g0   = (lane >> 4);
    const int a_base = a_row * 64;
    const int a_r7   = a_row & 7;
    const int b_rowL = (lane & 7) + ((lane & 16) ? 8 : 0);
    const int b_g0   = (lane & 8) ? 1 : 0;
    int b_base[2], b_r7[2];
    #pragma unroll
    for (int p = 0; p < 2; p++) {
        const int brow = nv * 32 + p * 16 + b_rowL;
        b_base[p] = brow * 512;
        b_r7[p]   = brow & 7;
    }
    const int r_base = mw * 16 + (lane >> 2);

    // ================= epilogue per-thread state =================
    float hp[3], br_[3], bz_[3], bni_[3], bnh_[3];
    int   ooff[3];
    #pragma unroll
    for (int n = 0; n < 3; n++) {
        const int e = tid + THR * n;
        if (e < 1024) {
            const int b  = e >> 4;
            const int j  = e & 15;
            const int jg = jb * 16 + j;
            ooff[n] = (b0 + b) * HH + jg;
            br_[n]  = b_ih[jg] + b_hh[jg];
            bz_[n]  = b_ih[HH + jg] + b_hh[HH + jg];
            bni_[n] = b_ih[2 * HH + jg];
            bnh_[n] = b_hh[2 * HH + jg];
            hp[n]   = hist[ooff[n]];
        }
    }

    CP_WAIT(0);
    __syncthreads();

    float acc[4][4];
    #pragma unroll
    for (int f = 0; f < 4; f++)
        #pragma unroll
        for (int i = 0; i < 4; i++) acc[f][i] = 0.0f;

    float* sG = (float*)(dsm + OFF_A);   // [64][100] gate exchange (aliases A)

    for (int t = 1; t < TT; t++) {
        const __nv_bfloat16* srcH = hh_base + (size_t)((t - 1) & 1) * BB * HH;
        const __nv_bfloat16* srcL = hl_base + (size_t)((t - 1) & 1) * BB * HH;
        const unsigned int need = (unsigned int)(t - 1);

        // ---- wait for chunk-0 producers (blocks 0..3 of this bq group) ----
        if (tid < 4) {
            const unsigned int* f = &g_flags[(bq * 32 + tid) * 32];
            while (ld_acq(f) < need) {}
        }
        __syncthreads();     // poll visible to all; also fences sG reuse

        // prologue: chunk 0 -> buf 0
        {
            __nv_bfloat16* buf = dsm + OFF_A;
            cp_async16(buf + aDst[0], (aMat[0] ? srcL : srcH) + aSrc[0]);
            cp_async16(buf + aDst[1], (aMat[1] ? srcL : srcH) + aSrc[1]);
            if (a3)
                cp_async16(buf + aDst[2], (aMat[2] ? srcL : srcH) + aSrc[2]);
            CP_COMMIT();
        }

        #pragma unroll 1
        for (int c = 0; c < NCH; c++) {
            // poll producers of NEXT chunk while this chunk's data lands
            if (c + 1 < NCH && tid < 4) {
                const unsigned int* f =
                    &g_flags[(bq * 32 + 4 * (c + 1) + tid) * 32];
                while (ld_acq(f) < need) {}
            }
            CP_WAIT(0);
            __syncthreads();

            if (c + 1 < NCH) {
                __nv_bfloat16* buf = dsm + OFF_A + ((c + 1) & 1) * A_BUF;
                const int k0 = (c + 1) * 64;
                cp_async16(buf + aDst[0], (aMat[0] ? srcL : srcH) + aSrc[0] + k0);
                cp_async16(buf + aDst[1], (aMat[1] ? srcL : srcH) + aSrc[1] + k0);
                if (a3)
                    cp_async16(buf + aDst[2], (aMat[2] ? srcL : srcH) + aSrc[2] + k0);
                CP_COMMIT();
            }

            const __nv_bfloat16* bufA = dsm + OFF_A + (c & 1) * A_BUF;
            #pragma unroll
            for (int q = 0; q < 4; q++) {
                uint32_t aH[4], aL[4];
                const int gsA = ((2 * q + a_g0) ^ a_r7) * 8;
                ldsm4(aH, bufA + a_base + gsA);
                ldsm4(aL, bufA + A_MATS + a_base + gsA);
                const int gqB = c * 8 + 2 * q + b_g0;
                #pragma unroll
                for (int p = 0; p < 2; p++) {
                    const int gsB = (gqB & 56) | ((gqB ^ b_r7[p]) & 7);
                    const int off = b_base[p] + gsB * 8;
                    uint32_t bh[4], bl[4];
                    ldsm4(bh, dsm + off);
                    ldsm4(bl, dsm + B_MATS + off);
                    mma_bf16(acc[2 * p],     aH, bh[0], bh[1]);
                    mma_bf16(acc[2 * p],     aH, bl[0], bl[1]);
                    mma_bf16(acc[2 * p],     aL, bh[0], bh[1]);
                    mma_bf16(acc[2 * p + 1], aH, bh[2], bh[3]);
                    mma_bf16(acc[2 * p + 1], aH, bl[2], bl[3]);
                    mma_bf16(acc[2 * p + 1], aL, bh[2], bh[3]);
                }
            }
        }
        __syncthreads();     // all chunk-7 LDSM done before sG overwrite

        // ---- write fragments to sG[64][100] ----
        {
            #pragma unroll
            for (int f = 0; f < 4; f++) {
                const int cb = nv * 32 + f * 8 + (lane & 3) * 2;
                sG[r_base * 100 + cb]           = acc[f][0];
                sG[r_base * 100 + cb + 1]       = acc[f][1];
                sG[(r_base + 8) * 100 + cb]     = acc[f][2];
                sG[(r_base + 8) * 100 + cb + 1] = acc[f][3];
            }
        }
        __syncthreads();

        // ---- gate epilogue ----
        {
            __nv_bfloat16* dstH = hh_base + (size_t)(t & 1) * BB * HH;
            __nv_bfloat16* dstL = hl_base + (size_t)(t & 1) * BB * HH;
            float* hout = hist + (size_t)t * BB * HH;
            #pragma unroll
            for (int n = 0; n < 3; n++) {
                const int e = tid + THR * n;
                if (e < 1024) {
                    const int b = e >> 4, j = e & 15;
                    const float gr = sG[b * 100 + j];
                    const float gz = sG[b * 100 + 16 + j];
                    const float gn = sG[b * 100 + 32 + j];
                    const float hr = sG[b * 100 + 48 + j];
                    const float hz = sG[b * 100 + 64 + j];
                    const float hn = sG[b * 100 + 80 + j];
                    const float rv = sigmoidf_(gr + hr + br_[n]);
                    const float zv = sigmoidf_(gz + hz + bz_[n]);
                    const float nn = tanhf(gn + bni_[n] + rv * (hn + bnh_[n]));
                    const float hv = (1.0f - zv) * nn + zv * hp[n];
                    hp[n] = hv;
                    hout[ooff[n]] = hv;
                    const __nv_bfloat16 hi = __float2bfloat16(hv);
                    dstH[ooff[n]] = hi;
                    dstL[ooff[n]] = __float2bfloat16(hv - __bfloat162float(hi));
                }
            }
        }

        // reset accumulators
        #pragma unroll
        for (int f = 0; f < 4; f++)
            #pragma unroll
            for (int i = 0; i < 4; i++) acc[f][i] = 0.0f;

        __syncthreads();     // all epilogue stores done (and sG reads done)
        if (tid == 0) st_rel(my_flag, (unsigned int)t);   // publish step t
    }
}

// ---------------------------------------------------------------------------
// Generic fp32 GRU step — used only for t = 0 (x = embed row, h = feat).
// ---------------------------------------------------------------------------
__global__ __launch_bounds__(256) void gru_step_kernel(
    const float* __restrict__ x, int xs,
    const float* __restrict__ h,
    const float* __restrict__ w_ih,
    const float* __restrict__ w_hh,
    const float* __restrict__ b_ih,
    const float* __restrict__ b_hh,
    float* __restrict__ h_out)
{
    __shared__ float sX[32][32];
    __shared__ float sH[32][32];
    __shared__ float sWih[3][32][32];
    __shared__ float sWhh[3][32][32];

    const int tid = threadIdx.x;
    const int tj  = tid & 31;
    const int tb  = tid >> 5;
    const int j0  = blockIdx.x * 32;
    const int b0  = blockIdx.y * 32;

    float acc[4][6];
    #pragma unroll
    for (int i = 0; i < 4; i++)
        #pragma unroll
        for (int g = 0; g < 6; g++) acc[i][g] = 0.0f;

    const int lb  = tid >> 3;
    const int lk4 = (tid & 7) * 4;

    for (int k0 = 0; k0 < HH; k0 += 32) {
        float4 xv4 = *(const float4*)(x + (size_t)(b0 + lb) * (size_t)xs + k0 + lk4);
        *(float4*)&sX[lb][lk4] = xv4;
        float4 hv4 = *(const float4*)(h + (size_t)(b0 + lb) * HH + k0 + lk4);
        *(float4*)&sH[lb][lk4] = hv4;
        #pragma unroll
        for (int g = 0; g < 3; g++) {
            float4 wi = *(const float4*)(w_ih + (size_t)(g * HH + j0 + lb) * HH + k0 + lk4);
            sWih[g][lk4 + 0][lb] = wi.x;
            sWih[g][lk4 + 1][lb] = wi.y;
            sWih[g][lk4 + 2][lb] = wi.z;
            sWih[g][lk4 + 3][lb] = wi.w;
            float4 wh = *(const float4*)(w_hh + (size_t)(g * HH + j0 + lb) * HH + k0 + lk4);
            sWhh[g][lk4 + 0][lb] = wh.x;
            sWhh[g][lk4 + 1][lb] = wh.y;
            sWhh[g][lk4 + 2][lb] = wh.z;
            sWhh[g][lk4 + 3][lb] = wh.w;
        }
        __syncthreads();

        #pragma unroll
        for (int kk = 0; kk < 32; kk++) {
            const float wi0 = sWih[0][kk][tj];
            const float wi1 = sWih[1][kk][tj];
            const float wi2 = sWih[2][kk][tj];
            const float wh0 = sWhh[0][kk][tj];
            const float wh1 = sWhh[1][kk][tj];
            const float wh2 = sWhh[2][kk][tj];
            #pragma unroll
            for (int i = 0; i < 4; i++) {
                const float xv = sX[tb * 4 + i][kk];
                const float hv = sH[tb * 4 + i][kk];
                acc[i][0] += xv * wi0;
                acc[i][1] += xv * wi1;
                acc[i][2] += xv * wi2;
                acc[i][3] += hv * wh0;
                acc[i][4] += hv * wh1;
                acc[i][5] += hv * wh2;
            }
        }
        __syncthreads();
    }

    const int j = j0 + tj;
    const float bir  = b_ih[j],          bhr = b_hh[j];
    const float biz  = b_ih[HH + j],     bhz = b_hh[HH + j];
    const float bin_ = b_ih[2 * HH + j], bhn = b_hh[2 * HH + j];
    #pragma unroll
    for (int i = 0; i < 4; i++) {
        const int b = b0 + tb * 4 + i;
        const float r = sigmoidf_(acc[i][0] + bir + acc[i][3] + bhr);
        const float z = sigmoidf_(acc[i][1] + biz + acc[i][4] + bhz);
        const float n = tanhf(acc[i][2] + bin_ + r * (acc[i][5] + bhn));
        const float hp = h[(size_t)b * HH + j];
        h_out[(size_t)b * HH + j] = (1.0f - z) * n + z * hp;
    }
}

// ---------------------------------------------------------------------------
// Projection: out[b][v][t] = hist[t][b][:] . proj_w[v][:] + proj_b[v]
// ---------------------------------------------------------------------------
__global__ __launch_bounds__(512) void proj_kernel(
    const float* __restrict__ proj_w,
    const float* __restrict__ proj_b,
    float* __restrict__ out)
{
    __shared__ float sH[TT][33];
    __shared__ float sW[VV][33];

    const int b   = blockIdx.x;
    const int tid = threadIdx.x;
    const int tg  = tid % 25;
    const int vg  = tid / 25;
    const bool active = (tid < 500);

    float acc[8][5];
    #pragma unroll
    for (int i = 0; i < 8; i++)
        #pragma unroll
        for (int jv = 0; jv < 5; jv++) acc[i][jv] = 0.0f;

    for (int k0 = 0; k0 < HH; k0 += 32) {
        for (int idx = tid; idx < TT * 32; idx += 512) {
            const int t = idx >> 5, k = idx & 31;
            sH[t][k] = g_hist[((size_t)t * BB + b) * HH + k0 + k];
        }
        for (int idx = tid; idx < VV * 32; idx += 512) {
            const int v = idx >> 5, k = idx & 31;
            sW[v][k] = proj_w[(size_t)v * HH + k0 + k];
        }
        __syncthreads();

        if (active) {
            #pragma unroll
            for (int kk = 0; kk < 32; kk++) {
                float wv[5];
                #pragma unroll
                for (int jv = 0; jv < 5; jv++) wv[jv] = sW[vg * 5 + jv][kk];
                #pragma unroll
                for (int i = 0; i < 8; i++) {
                    const float hv = sH[tg + 25 * i][kk];
                    #pragma unroll
                    for (int jv = 0; jv < 5; jv++) acc[i][jv] += hv * wv[jv];
                }
            }
        }
        __syncthreads();
    }

    if (active) {
        float pb[5];
        #pragma unroll
        for (int jv = 0; jv < 5; jv++) pb[jv] = proj_b[vg * 5 + jv];
        #pragma unroll
        for (int i = 0; i < 8; i++) {
            const int t = tg + 25 * i;
            #pragma unroll
            for (int jv = 0; jv < 5; jv++) {
                const int v = vg * 5 + jv;
                out[((size_t)b * VV + v) * TT + t] = acc[i][jv] + pb[jv];
            }
        }
    }
}

// ---------------------------------------------------------------------------
extern "C" void kernel_launch(void* const* d_in, const int* in_sizes, int n_in,
                              void* d_out, int out_size)
{
    (void)in_sizes; (void)n_in; (void)out_size;
    const float* feat   = (const float*)d_in[0];
    const float* embed  = (const float*)d_in[1];
    const float* w_ih   = (const float*)d_in[2];
    const float* w_hh   = (const float*)d_in[3];
    const float* b_ih   = (const float*)d_in[4];
    const float* b_hh   = (const float*)d_in[5];
    const float* proj_w = (const float*)d_in[6];
    const float* proj_b = (const float*)d_in[7];
    float* out = (float*)d_out;

    float* hist = nullptr;
    cudaGetSymbolAddress((void**)&hist, g_hist);
    __nv_bfloat16* hhp = nullptr;
    cudaGetSymbolAddress((void**)&hhp, g_hh);
    __nv_bfloat16* hlp = nullptr;
    cudaGetSymbolAddress((void**)&hlp, g_hl);

    cudaFuncSetAttribute(gru_persistent,
                         cudaFuncAttributeMaxDynamicSharedMemorySize, SMEM_P);

    prep_weights<<<(6 * HH * HH + 255) / 256, 256>>>(w_ih, w_hh);
    reset_flags_kernel<<<4, 1024>>>();

    // step 0: x = embed[SOS=0] broadcast, h = feat  -> hist[0]
    gru_step_kernel<<<dim3(HH / 32, BB / 32), 256>>>(embed, 0, feat,
                                                     w_ih, w_hh, b_ih, b_hh, hist);
    convert_h<<<(BB * HH + 255) / 256, 256>>>(hist, hhp, hlp);   // -> pp slot 0

    // steps 1..199: persistent tensor-core kernel (one wave of 128 blocks)
    gru_persistent<<<dim3(32, 4), THR, SMEM_P>>>(b_ih, b_hh, hist, hhp, hlp);

    proj_kernel<<<BB, 512>>>(proj_w, proj_b, out);
}

// round 9
// speedup vs baseline: 1.0038x; 1.0038x over previous
#include <cuda_runtime.h>
#include <cuda_bf16.h>
#include <stdint.h>
#include <math.h>

#define BB 256     // batch
#define HH 512     // hidden
#define VV 100     // vocab
#define TT 200     // steps

// fp32 hidden-state history (proj + epilogue need fp32 h)
__device__ float g_hist[(size_t)TT * BB * HH];
// bf16 hi/lo ping-pong of previous hidden state
__device__ __nv_bfloat16 g_hh[2][BB * HH];
__device__ __nv_bfloat16 g_hl[2][BB * HH];
// packed weights: row n = jb*96 + g*16 + j  (jb=0..31, g=0..5, j=0..15), k=0..511
__device__ __nv_bfloat16 g_wh[6 * HH * HH];
__device__ __nv_bfloat16 g_wl[6 * HH * HH];
// per-block progress flags: g_flags[(bq*32 + jb)*32] = last step published
__device__ unsigned int g_flags[4 * 32 * 32];

__device__ __forceinline__ float sigmoidf_(float x) {
    return 1.0f / (1.0f + expf(-x));
}
// fast epilogue math (MUFU-based)
__device__ __forceinline__ float fast_sig(float x) {
    return 1.0f / (1.0f + __expf(-x));
}
__device__ __forceinline__ float fast_tanh(float x) {
    return 2.0f / (1.0f + __expf(-2.0f * x)) - 1.0f;
}

// ---------------------------------------------------------------------------
// async / mma / sync helpers
// ---------------------------------------------------------------------------
__device__ __forceinline__ void cp_async16(void* smem_dst, const void* gmem_src) {
    unsigned int s = (unsigned int)__cvta_generic_to_shared(smem_dst);
    asm volatile("cp.async.cg.shared.global [%0], [%1], 16;\n" :: "r"(s), "l"(gmem_src));
}
#define CP_COMMIT() asm volatile("cp.async.commit_group;\n" ::: "memory")
#define CP_WAIT(n)  asm volatile("cp.async.wait_group %0;\n" :: "n"(n) : "memory")

__device__ __forceinline__ void ldsm4(uint32_t r[4], const void* p) {
    unsigned int s = (unsigned int)__cvta_generic_to_shared(p);
    asm volatile("ldmatrix.sync.aligned.m8n8.x4.shared.b16 {%0,%1,%2,%3}, [%4];"
                 : "=r"(r[0]), "=r"(r[1]), "=r"(r[2]), "=r"(r[3]) : "r"(s));
}

__device__ __forceinline__ void mma_bf16(float d[4], const uint32_t a[4],
                                         uint32_t b0, uint32_t b1) {
    asm volatile(
        "mma.sync.aligned.m16n8k16.row.col.f32.bf16.bf16.f32 "
        "{%0,%1,%2,%3}, {%4,%5,%6,%7}, {%8,%9}, {%0,%1,%2,%3};"
        : "+f"(d[0]), "+f"(d[1]), "+f"(d[2]), "+f"(d[3])
        : "r"(a[0]), "r"(a[1]), "r"(a[2]), "r"(a[3]), "r"(b0), "r"(b1));
}

__device__ __forceinline__ unsigned int ld_acq(const unsigned int* p) {
    unsigned int v;
    asm volatile("ld.acquire.gpu.u32 %0, [%1];" : "=r"(v) : "l"(p));
    return v;
}
__device__ __forceinline__ void st_rel(unsigned int* p, unsigned int v) {
    asm volatile("st.release.gpu.u32 [%0], %1;" :: "l"(p), "r"(v));
}

// ---------------------------------------------------------------------------
// One-time weight prep: pack + split fp32 -> bf16 hi/lo.
// ---------------------------------------------------------------------------
__global__ __launch_bounds__(256) void prep_weights(
    const float* __restrict__ w_ih, const float* __restrict__ w_hh)
{
    int idx = blockIdx.x * 256 + threadIdx.x;
    if (idx >= 6 * HH * HH) return;
    int n = idx / HH, k = idx % HH;
    int jb = n / 96, rr = n % 96, g = rr / 16, j = rr % 16;
    const float* src = (g < 3) ? w_ih : w_hh;
    float v = src[(size_t)((g % 3) * HH + jb * 16 + j) * HH + k];
    __nv_bfloat16 hi = __float2bfloat16(v);
    g_wh[idx] = hi;
    g_wl[idx] = __float2bfloat16(v - __bfloat162float(hi));
}

__global__ __launch_bounds__(1024) void reset_flags_kernel() {
    int i = blockIdx.x * 1024 + threadIdx.x;
    if (i < 4 * 32 * 32) g_flags[i] = 0u;
}

// ---------------------------------------------------------------------------
// Convert fp32 h -> bf16 hi/lo (after step 0)
// ---------------------------------------------------------------------------
__global__ __launch_bounds__(256) void convert_h(
    const float* __restrict__ h, __nv_bfloat16* __restrict__ hh,
    __nv_bfloat16* __restrict__ hl)
{
    int idx = blockIdx.x * 256 + threadIdx.x;
    if (idx >= BB * HH) return;
    float v = h[idx];
    __nv_bfloat16 hi = __float2bfloat16(v);
    hh[idx] = hi;
    hl[idx] = __float2bfloat16(v - __bfloat162float(hi));
}

// ---------------------------------------------------------------------------
// Persistent tensor-core GRU, v4: R7's pipelined chunk loop + fine-grained
// producer flags polled one chunk AHEAD (inside existing sync envelope).
// Grid (32 jb, 4 bq) = 128 blocks, 384 threads (12 warps: 4 mw x 3 nv(n=32)).
// B tile (96x512, hi+lo) XOR-swizzled, SMEM-resident whole kernel.
// A (h hi/lo) streamed per step, k=64 chunks, double buffer (1 group in flight).
// ---------------------------------------------------------------------------
#define THR    384
#define B_MATS (96 * 512)                   // bf16 per B matrix (swizzled, no pad)
#define OFF_A  (2 * B_MATS)                 // 98304 bf16
#define A_MATS (64 * 64)                    // bf16 per A matrix per chunk (k=64)
#define A_BUF  (2 * A_MATS)                 // hi+lo per buffer = 8192 bf16
#define SMEM_P ((OFF_A + 2 * A_BUF) * 2)    // 229376 bytes (224 KB)
#define NCH    8                            // K chunks of 64

__global__ __launch_bounds__(THR) void gru_persistent(
    const float* __restrict__ b_ih,
    const float* __restrict__ b_hh,
    float* __restrict__ hist,                 // [TT][BB][HH]
    __nv_bfloat16* __restrict__ hh_base,      // [2][BB*HH]
    __nv_bfloat16* __restrict__ hl_base)
{
    extern __shared__ __align__(16) __nv_bfloat16 dsm[];

    const int tid  = threadIdx.x;
    const int lane = tid & 31;
    const int w    = tid >> 5;           // 0..11
    const int mw   = w & 3;              // m16 tile
    const int nv   = w >> 2;             // 0..2, n=32 each
    const int jb   = blockIdx.x;         // 0..31
    const int bq   = blockIdx.y;         // 0..3
    const int b0   = bq * 64;

    unsigned int* my_flag = &g_flags[(bq * 32 + jb) * 32];

    // ================= resident B load (swizzled, once) =================
    for (int i = tid; i < 2 * 96 * 64; i += THR) {     // 16B granules
        const int mat = i / (96 * 64);
        const int rr  = i % (96 * 64);
        const int row = rr >> 6;
        const int g   = rr & 63;
        const int gs  = (g & 56) | ((g ^ row) & 7);
        const __nv_bfloat16* src =
            (mat ? g_wl : g_wh) + (size_t)(jb * 96 + row) * HH + g * 8;
        cp_async16(dsm + mat * B_MATS + row * 512 + gs * 8, src);
    }
    CP_COMMIT();

    // ========== per-thread A-chunk cp.async descriptors (<=3 each) =========
    int aMat[3], aDst[3], aSrc[3];
    #pragma unroll
    for (int k = 0; k < 3; k++) {
        const int i = tid + THR * k;
        if (i < 1024) {
            const int mat = i >> 9;
            const int r   = (i >> 3) & 63;
            const int g   = i & 7;
            aMat[k] = mat;
            aDst[k] = mat * A_MATS + r * 64 + ((g ^ (r & 7)) * 8);
            aSrc[k] = (b0 + r) * HH + g * 8;
        }
    }
    const bool a3 = (tid + 2 * THR < 1024);

    // ================= ldmatrix lane invariants =================
    const int a_row  = mw * 16 + (lane & 15);
    const int a_g0   = (lane >> 4);
    const int a_base = a_row * 64;
    const int a_r7   = a_row & 7;
    const int b_rowL = (lane & 7) + ((lane & 16) ? 8 : 0);
    const int b_g0   = (lane & 8) ? 1 : 0;
    int b_base[2], b_r7[2];
    #pragma unroll
    for (int p = 0; p < 2; p++) {
        const int brow = nv * 32 + p * 16 + b_rowL;
        b_base[p] = brow * 512;
        b_r7[p]   = brow & 7;
    }
    const int r_base = mw * 16 + (lane >> 2);

    // ================= epilogue per-thread state =================
    float hp[3], br_[3], bz_[3], bni_[3], bnh_[3];
    int   ooff[3];
    #pragma unroll
    for (int n = 0; n < 3; n++) {
        const int e = tid + THR * n;
        if (e < 1024) {
            const int b  = e >> 4;
            const int j  = e & 15;
            const int jg = jb * 16 + j;
            ooff[n] = (b0 + b) * HH + jg;
            br_[n]  = b_ih[jg] + b_hh[jg];
            bz_[n]  = b_ih[HH + jg] + b_hh[HH + jg];
            bni_[n] = b_ih[2 * HH + jg];
            bnh_[n] = b_hh[2 * HH + jg];
            hp[n]   = hist[ooff[n]];
        }
    }

    CP_WAIT(0);
    __syncthreads();

    float acc[4][4];
    #pragma unroll
    for (int f = 0; f < 4; f++)
        #pragma unroll
        for (int i = 0; i < 4; i++) acc[f][i] = 0.0f;

    float* sG = (float*)(dsm + OFF_A);   // [64][100] gate exchange (aliases A)

    for (int t = 1; t < TT; t++) {
        const __nv_bfloat16* srcH = hh_base + (size_t)((t - 1) & 1) * BB * HH;
        const __nv_bfloat16* srcL = hl_base + (size_t)((t - 1) & 1) * BB * HH;
        const unsigned int need = (unsigned int)(t - 1);

        // ---- poll producers of chunks 0 and 1 (blocks 0..7 of this group) ----
        if (tid < 8) {
            const unsigned int* f = &g_flags[(bq * 32 + tid) * 32];
            while (ld_acq(f) < need) {}
        }
        __syncthreads();     // poll visible; also fences sG reuse vs chunk-0 write

        // prologue: chunk 0 -> buf 0
        {
            __nv_bfloat16* buf = dsm + OFF_A;
            cp_async16(buf + aDst[0], (aMat[0] ? srcL : srcH) + aSrc[0]);
            cp_async16(buf + aDst[1], (aMat[1] ? srcL : srcH) + aSrc[1]);
            if (a3)
                cp_async16(buf + aDst[2], (aMat[2] ? srcL : srcH) + aSrc[2]);
            CP_COMMIT();
        }

        #pragma unroll 1
        for (int c = 0; c < NCH; c++) {
            // commit chunk c+1 FIRST (producers polled one iteration ago),
            // keeping one cp.async group always in flight.
            if (c + 1 < NCH) {
                __nv_bfloat16* buf = dsm + OFF_A + ((c + 1) & 1) * A_BUF;
                const int k0 = (c + 1) * 64;
                cp_async16(buf + aDst[0], (aMat[0] ? srcL : srcH) + aSrc[0] + k0);
                cp_async16(buf + aDst[1], (aMat[1] ? srcL : srcH) + aSrc[1] + k0);
                if (a3)
                    cp_async16(buf + aDst[2], (aMat[2] ? srcL : srcH) + aSrc[2] + k0);
                CP_COMMIT();
                CP_WAIT(1);
            } else {
                CP_WAIT(0);
            }
            __syncthreads();

            const __nv_bfloat16* bufA = dsm + OFF_A + (c & 1) * A_BUF;
            #pragma unroll
            for (int q = 0; q < 4; q++) {
                uint32_t aH[4], aL[4];
                const int gsA = ((2 * q + a_g0) ^ a_r7) * 8;
                ldsm4(aH, bufA + a_base + gsA);
                ldsm4(aL, bufA + A_MATS + a_base + gsA);
                const int gqB = c * 8 + 2 * q + b_g0;
                #pragma unroll
                for (int p = 0; p < 2; p++) {
                    const int gsB = (gqB & 56) | ((gqB ^ b_r7[p]) & 7);
                    const int off = b_base[p] + gsB * 8;
                    uint32_t bh[4], bl[4];
                    ldsm4(bh, dsm + off);
                    ldsm4(bl, dsm + B_MATS + off);
                    mma_bf16(acc[2 * p],     aH, bh[0], bh[1]);
                    mma_bf16(acc[2 * p],     aH, bl[0], bl[1]);
                    mma_bf16(acc[2 * p],     aL, bh[0], bh[1]);
                    mma_bf16(acc[2 * p + 1], aH, bh[2], bh[3]);
                    mma_bf16(acc[2 * p + 1], aH, bl[2], bl[3]);
                    mma_bf16(acc[2 * p + 1], aL, bh[2], bh[3]);
                }
            }
            // poll producers of chunk c+2 (covered by the trailing sync)
            if (c + 2 < NCH && tid < 4) {
                const unsigned int* f =
                    &g_flags[(bq * 32 + 4 * (c + 2) + tid) * 32];
                while (ld_acq(f) < need) {}
            }
            __syncthreads();   // buffer consumed + polls visible
        }

        // ---- write fragments to sG[64][100] ----
        {
            #pragma unroll
            for (int f = 0; f < 4; f++) {
                const int cb = nv * 32 + f * 8 + (lane & 3) * 2;
                sG[r_base * 100 + cb]           = acc[f][0];
                sG[r_base * 100 + cb + 1]       = acc[f][1];
                sG[(r_base + 8) * 100 + cb]     = acc[f][2];
                sG[(r_base + 8) * 100 + cb + 1] = acc[f][3];
            }
        }
        __syncthreads();

        // ---- gate epilogue (fast MUFU math) ----
        {
            __nv_bfloat16* dstH = hh_base + (size_t)(t & 1) * BB * HH;
            __nv_bfloat16* dstL = hl_base + (size_t)(t & 1) * BB * HH;
            float* hout = hist + (size_t)t * BB * HH;
            #pragma unroll
            for (int n = 0; n < 3; n++) {
                const int e = tid + THR * n;
                if (e < 1024) {
                    const int b = e >> 4, j = e & 15;
                    const float gr = sG[b * 100 + j];
                    const float gz = sG[b * 100 + 16 + j];
                    const float gn = sG[b * 100 + 32 + j];
                    const float hr = sG[b * 100 + 48 + j];
                    const float hz = sG[b * 100 + 64 + j];
                    const float hn = sG[b * 100 + 80 + j];
                    const float rv = fast_sig(gr + hr + br_[n]);
                    const float zv = fast_sig(gz + hz + bz_[n]);
                    const float nn = fast_tanh(gn + bni_[n] + rv * (hn + bnh_[n]));
                    const float hv = (1.0f - zv) * nn + zv * hp[n];
                    hp[n] = hv;
                    hout[ooff[n]] = hv;
                    const __nv_bfloat16 hi = __float2bfloat16(hv);
                    dstH[ooff[n]] = hi;
                    dstL[ooff[n]] = __float2bfloat16(hv - __bfloat162float(hi));
                }
            }
        }

        // reset accumulators
        #pragma unroll
        for (int f = 0; f < 4; f++)
            #pragma unroll
            for (int i = 0; i < 4; i++) acc[f][i] = 0.0f;

        __syncthreads();     // all epilogue stores done (and sG reads done)
        if (tid == 0) st_rel(my_flag, (unsigned int)t);   // publish step t
    }
}

// ---------------------------------------------------------------------------
// Generic fp32 GRU step — used only for t = 0 (x = embed row, h = feat).
// ---------------------------------------------------------------------------
__global__ __launch_bounds__(256) void gru_step_kernel(
    const float* __restrict__ x, int xs,
    const float* __restrict__ h,
    const float* __restrict__ w_ih,
    const float* __restrict__ w_hh,
    const float* __restrict__ b_ih,
    const float* __restrict__ b_hh,
    float* __restrict__ h_out)
{
    __shared__ float sX[32][32];
    __shared__ float sH[32][32];
    __shared__ float sWih[3][32][32];
    __shared__ float sWhh[3][32][32];

    const int tid = threadIdx.x;
    const int tj  = tid & 31;
    const int tb  = tid >> 5;
    const int j0  = blockIdx.x * 32;
    const int b0  = blockIdx.y * 32;

    float acc[4][6];
    #pragma unroll
    for (int i = 0; i < 4; i++)
        #pragma unroll
        for (int g = 0; g < 6; g++) acc[i][g] = 0.0f;

    const int lb  = tid >> 3;
    const int lk4 = (tid & 7) * 4;

    for (int k0 = 0; k0 < HH; k0 += 32) {
        float4 xv4 = *(const float4*)(x + (size_t)(b0 + lb) * (size_t)xs + k0 + lk4);
        *(float4*)&sX[lb][lk4] = xv4;
        float4 hv4 = *(const float4*)(h + (size_t)(b0 + lb) * HH + k0 + lk4);
        *(float4*)&sH[lb][lk4] = hv4;
        #pragma unroll
        for (int g = 0; g < 3; g++) {
            float4 wi = *(const float4*)(w_ih + (size_t)(g * HH + j0 + lb) * HH + k0 + lk4);
            sWih[g][lk4 + 0][lb] = wi.x;
            sWih[g][lk4 + 1][lb] = wi.y;
            sWih[g][lk4 + 2][lb] = wi.z;
            sWih[g][lk4 + 3][lb] = wi.w;
            float4 wh = *(const float4*)(w_hh + (size_t)(g * HH + j0 + lb) * HH + k0 + lk4);
            sWhh[g][lk4 + 0][lb] = wh.x;
            sWhh[g][lk4 + 1][lb] = wh.y;
            sWhh[g][lk4 + 2][lb] = wh.z;
            sWhh[g][lk4 + 3][lb] = wh.w;
        }
        __syncthreads();

        #pragma unroll
        for (int kk = 0; kk < 32; kk++) {
            const float wi0 = sWih[0][kk][tj];
            const float wi1 = sWih[1][kk][tj];
            const float wi2 = sWih[2][kk][tj];
            const float wh0 = sWhh[0][kk][tj];
            const float wh1 = sWhh[1][kk][tj];
            const float wh2 = sWhh[2][kk][tj];
            #pragma unroll
            for (int i = 0; i < 4; i++) {
                const float xv = sX[tb * 4 + i][kk];
                const float hv = sH[tb * 4 + i][kk];
                acc[i][0] += xv * wi0;
                acc[i][1] += xv * wi1;
                acc[i][2] += xv * wi2;
                acc[i][3] += hv * wh0;
                acc[i][4] += hv * wh1;
                acc[i][5] += hv * wh2;
            }
        }
        __syncthreads();
    }

    const int j = j0 + tj;
    const float bir  = b_ih[j],          bhr = b_hh[j];
    const float biz  = b_ih[HH + j],     bhz = b_hh[HH + j];
    const float bin_ = b_ih[2 * HH + j], bhn = b_hh[2 * HH + j];
    #pragma unroll
    for (int i = 0; i < 4; i++) {
        const int b = b0 + tb * 4 + i;
        const float r = sigmoidf_(acc[i][0] + bir + acc[i][3] + bhr);
        const float z = sigmoidf_(acc[i][1] + biz + acc[i][4] + bhz);
        const float n = tanhf(acc[i][2] + bin_ + r * (acc[i][5] + bhn));
        const float hp = h[(size_t)b * HH + j];
        h_out[(size_t)b * HH + j] = (1.0f - z) * n + z * hp;
    }
}

// ---------------------------------------------------------------------------
// Projection: out[b][v][t] = hist[t][b][:] . proj_w[v][:] + proj_b[v]
// ---------------------------------------------------------------------------
__global__ __launch_bounds__(512) void proj_kernel(
    const float* __restrict__ proj_w,
    const float* __restrict__ proj_b,
    float* __restrict__ out)
{
    __shared__ float sH[TT][33];
    __shared__ float sW[VV][33];

    const int b   = blockIdx.x;
    const int tid = threadIdx.x;
    const int tg  = tid % 25;
    const int vg  = tid / 25;
    const bool active = (tid < 500);

    float acc[8][5];
    #pragma unroll
    for (int i = 0; i < 8; i++)
        #pragma unroll
        for (int jv = 0; jv < 5; jv++) acc[i][jv] = 0.0f;

    for (int k0 = 0; k0 < HH; k0 += 32) {
        for (int idx = tid; idx < TT * 32; idx += 512) {
            const int t = idx >> 5, k = idx & 31;
            sH[t][k] = g_hist[((size_t)t * BB + b) * HH + k0 + k];
        }
        for (int idx = tid; idx < VV * 32; idx += 512) {
            const int v = idx >> 5, k = idx & 31;
            sW[v][k] = proj_w[(size_t)v * HH + k0 + k];
        }
        __syncthreads();

        if (active) {
            #pragma unroll
            for (int kk = 0; kk < 32; kk++) {
                float wv[5];
                #pragma unroll
                for (int jv = 0; jv < 5; jv++) wv[jv] = sW[vg * 5 + jv][kk];
                #pragma unroll
                for (int i = 0; i < 8; i++) {
                    const float hv = sH[tg + 25 * i][kk];
                    #pragma unroll
                    for (int jv = 0; jv < 5; jv++) acc[i][jv] += hv * wv[jv];
                }
            }
        }
        __syncthreads();
    }

    if (active) {
        float pb[5];
        #pragma unroll
        for (int jv = 0; jv < 5; jv++) pb[jv] = proj_b[vg * 5 + jv];
        #pragma unroll
        for (int i = 0; i < 8; i++) {
            const int t = tg + 25 * i;
            #pragma unroll
            for (int jv = 0; jv < 5; jv++) {
                const int v = vg * 5 + jv;
                out[((size_t)b * VV + v) * TT + t] = acc[i][jv] + pb[jv];
            }
        }
    }
}

// ---------------------------------------------------------------------------
extern "C" void kernel_launch(void* const* d_in, const int* in_sizes, int n_in,
                              void* d_out, int out_size)
{
    (void)in_sizes; (void)n_in; (void)out_size;
    const float* feat   = (const float*)d_in[0];
    const float* embed  = (const float*)d_in[1];
    const float* w_ih   = (const float*)d_in[2];
    const float* w_hh   = (const float*)d_in[3];
    const float* b_ih   = (const float*)d_in[4];
    const float* b_hh   = (const float*)d_in[5];
    const float* proj_w = (const float*)d_in[6];
    const float* proj_b = (const float*)d_in[7];
    float* out = (float*)d_out;

    float* hist = nullptr;
    cudaGetSymbolAddress((void**)&hist, g_hist);
    __nv_bfloat16* hhp = nullptr;
    cudaGetSymbolAddress((void**)&hhp, g_hh);
    __nv_bfloat16* hlp = nullptr;
    cudaGetSymbolAddress((void**)&hlp, g_hl);

    cudaFuncSetAttribute(gru_persistent,
                         cudaFuncAttributeMaxDynamicSharedMemorySize, SMEM_P);

    prep_weights<<<(6 * HH * HH + 255) / 256, 256>>>(w_ih, w_hh);
    reset_flags_kernel<<<4, 1024>>>();

    // step 0: x = embed[SOS=0] broadcast, h = feat  -> hist[0]
    gru_step_kernel<<<dim3(HH / 32, BB / 32), 256>>>(embed, 0, feat,
                                                     w_ih, w_hh, b_ih, b_hh, hist);
    convert_h<<<(BB * HH + 255) / 256, 256>>>(hist, hhp, hlp);   // -> pp slot 0

    // steps 1..199: persistent tensor-core kernel (one wave of 128 blocks)
    gru_persistent<<<dim3(32, 4), THR, SMEM_P>>>(b_ih, b_hh, hist, hhp, hlp);

    proj_kernel<<<BB, 512>>>(proj_w, proj_b, out);
}

// round 10
// speedup vs baseline: 1.2100x; 1.2055x over previous
#include <cuda_runtime.h>
#include <cuda_bf16.h>
#include <stdint.h>
#include <math.h>

#define BB 256     // batch
#define HH 512     // hidden
#define VV 100     // vocab
#define TT 200     // steps

// fp32 hidden-state history (proj + epilogue need fp32 h)
__device__ float g_hist[(size_t)TT * BB * HH];
// bf16 hi/lo ping-pong of previous hidden state
__device__ __nv_bfloat16 g_hh[2][BB * HH];
__device__ __nv_bfloat16 g_hl[2][BB * HH];
// packed weights: row n = jb*96 + g*16 + j  (jb=0..31, g=0..5, j=0..15), k=0..511
__device__ __nv_bfloat16 g_wh[6 * HH * HH];
__device__ __nv_bfloat16 g_wl[6 * HH * HH];
// per-batch-group step barrier counters
__device__ unsigned int g_ctrs[4];

__device__ __forceinline__ float sigmoidf_(float x) {
    return 1.0f / (1.0f + expf(-x));
}
// fast epilogue math (MUFU-based)
__device__ __forceinline__ float fast_sig(float x) {
    return 1.0f / (1.0f + __expf(-x));
}
__device__ __forceinline__ float fast_tanh(float x) {
    return 2.0f / (1.0f + __expf(-2.0f * x)) - 1.0f;
}

// ---------------------------------------------------------------------------
// async / mma / sync helpers
// ---------------------------------------------------------------------------
__device__ __forceinline__ void cp_async16(void* smem_dst, const void* gmem_src) {
    unsigned int s = (unsigned int)__cvta_generic_to_shared(smem_dst);
    asm volatile("cp.async.cg.shared.global [%0], [%1], 16;\n" :: "r"(s), "l"(gmem_src));
}
#define CP_COMMIT() asm volatile("cp.async.commit_group;\n" ::: "memory")
#define CP_WAIT(n)  asm volatile("cp.async.wait_group %0;\n" :: "n"(n) : "memory")

__device__ __forceinline__ void ldsm4(uint32_t r[4], const void* p) {
    unsigned int s = (unsigned int)__cvta_generic_to_shared(p);
    asm volatile("ldmatrix.sync.aligned.m8n8.x4.shared.b16 {%0,%1,%2,%3}, [%4];"
                 : "=r"(r[0]), "=r"(r[1]), "=r"(r[2]), "=r"(r[3]) : "r"(s));
}

__device__ __forceinline__ void mma_bf16(float d[4], const uint32_t a[4],
                                         uint32_t b0, uint32_t b1) {
    asm volatile(
        "mma.sync.aligned.m16n8k16.row.col.f32.bf16.bf16.f32 "
        "{%0,%1,%2,%3}, {%4,%5,%6,%7}, {%8,%9}, {%0,%1,%2,%3};"
        : "+f"(d[0]), "+f"(d[1]), "+f"(d[2]), "+f"(d[3])
        : "r"(a[0]), "r"(a[1]), "r"(a[2]), "r"(a[3]), "r"(b0), "r"(b1));
}

__device__ __forceinline__ unsigned int ld_acq(const unsigned int* p) {
    unsigned int v;
    asm volatile("ld.acquire.gpu.u32 %0, [%1];" : "=r"(v) : "l"(p));
    return v;
}
__device__ __forceinline__ void red_release_add(unsigned int* p, unsigned int v) {
    asm volatile("red.release.gpu.global.add.u32 [%0], %1;" :: "l"(p), "r"(v)
                 : "memory");
}

// ---------------------------------------------------------------------------
// One-time weight prep: pack + split fp32 -> bf16 hi/lo.
// ---------------------------------------------------------------------------
__global__ __launch_bounds__(256) void prep_weights(
    const float* __restrict__ w_ih, const float* __restrict__ w_hh)
{
    int idx = blockIdx.x * 256 + threadIdx.x;
    if (idx >= 6 * HH * HH) return;
    int n = idx / HH, k = idx % HH;
    int jb = n / 96, rr = n % 96, g = rr / 16, j = rr % 16;
    const float* src = (g < 3) ? w_ih : w_hh;
    float v = src[(size_t)((g % 3) * HH + jb * 16 + j) * HH + k];
    __nv_bfloat16 hi = __float2bfloat16(v);
    g_wh[idx] = hi;
    g_wl[idx] = __float2bfloat16(v - __bfloat162float(hi));
}

__global__ void reset_ctr_kernel() {
    if (threadIdx.x < 4) g_ctrs[threadIdx.x] = 0u;
}

// ---------------------------------------------------------------------------
// Convert fp32 h -> bf16 hi/lo (after step 0)
// ---------------------------------------------------------------------------
__global__ __launch_bounds__(256) void convert_h(
    const float* __restrict__ h, __nv_bfloat16* __restrict__ hh,
    __nv_bfloat16* __restrict__ hl)
{
    int idx = blockIdx.x * 256 + threadIdx.x;
    if (idx >= BB * HH) return;
    float v = h[idx];
    __nv_bfloat16 hi = __float2bfloat16(v);
    hh[idx] = hi;
    hl[idx] = __float2bfloat16(v - __bfloat162float(hi));
}

// ---------------------------------------------------------------------------
// Persistent tensor-core GRU (R7 structure, measured best) + MUFU epilogue
// + single-thread release barrier.
// Grid (32 jb, 4 bq) = 128 blocks, 384 threads (12 warps: 4 mw x 3 nv(n=32)).
// B tile (96x512, hi+lo) XOR-swizzled, SMEM-resident whole kernel.
// A (h hi/lo) streamed per step, k=64 chunks, double buffer.
// Step barrier: per-bq-group atomic counter (fan-in 32).
// ---------------------------------------------------------------------------
#define THR    384
#define B_MATS (96 * 512)                   // bf16 per B matrix (swizzled, no pad)
#define OFF_A  (2 * B_MATS)                 // 98304 bf16
#define A_MATS (64 * 64)                    // bf16 per A matrix per chunk (k=64)
#define A_BUF  (2 * A_MATS)                 // hi+lo per buffer = 8192 bf16
#define SMEM_P ((OFF_A + 2 * A_BUF) * 2)    // 229376 bytes (224 KB)
#define NCH    8                            // K chunks of 64

__global__ __launch_bounds__(THR) void gru_persistent(
    const float* __restrict__ b_ih,
    const float* __restrict__ b_hh,
    float* __restrict__ hist,                 // [TT][BB][HH]
    __nv_bfloat16* __restrict__ hh_base,      // [2][BB*HH]
    __nv_bfloat16* __restrict__ hl_base)
{
    extern __shared__ __align__(16) __nv_bfloat16 dsm[];

    const int tid  = threadIdx.x;
    const int lane = tid & 31;
    const int w    = tid >> 5;           // 0..11
    const int mw   = w & 3;              // m16 tile
    const int nv   = w >> 2;             // 0..2, n=32 each
    const int jb   = blockIdx.x;         // 0..31
    const int bq   = blockIdx.y;         // 0..3
    const int b0   = bq * 64;

    // ================= resident B load (swizzled, once) =================
    for (int i = tid; i < 2 * 96 * 64; i += THR) {     // 16B granules
        const int mat = i / (96 * 64);
        const int rr  = i % (96 * 64);
        const int row = rr >> 6;
        const int g   = rr & 63;
        const int gs  = (g & 56) | ((g ^ row) & 7);
        const __nv_bfloat16* src =
            (mat ? g_wl : g_wh) + (size_t)(jb * 96 + row) * HH + g * 8;
        cp_async16(dsm + mat * B_MATS + row * 512 + gs * 8, src);
    }
    CP_COMMIT();

    // ========== per-thread A-chunk cp.async descriptors (<=3 each) =========
    int aMat[3], aDst[3], aSrc[3];
    #pragma unroll
    for (int k = 0; k < 3; k++) {
        const int i = tid + THR * k;
        if (i < 1024) {
            const int mat = i >> 9;
            const int r   = (i >> 3) & 63;
            const int g   = i & 7;
            aMat[k] = mat;
            aDst[k] = mat * A_MATS + r * 64 + ((g ^ (r & 7)) * 8);
            aSrc[k] = (b0 + r) * HH + g * 8;
        }
    }
    const bool a3 = (tid + 2 * THR < 1024);

    // ================= ldmatrix lane invariants =================
    const int a_row  = mw * 16 + (lane & 15);
    const int a_g0   = (lane >> 4);
    const int a_base = a_row * 64;
    const int a_r7   = a_row & 7;
    const int b_rowL = (lane & 7) + ((lane & 16) ? 8 : 0);
    const int b_g0   = (lane & 8) ? 1 : 0;
    int b_base[2], b_r7[2];
    #pragma unroll
    for (int p = 0; p < 2; p++) {
        const int brow = nv * 32 + p * 16 + b_rowL;
        b_base[p] = brow * 512;
        b_r7[p]   = brow & 7;
    }
    const int r_base = mw * 16 + (lane >> 2);

    // ================= epilogue per-thread state =================
    float hp[3], br_[3], bz_[3], bni_[3], bnh_[3];
    int   ooff[3];
    #pragma unroll
    for (int n = 0; n < 3; n++) {
        const int e = tid + THR * n;
        if (e < 1024) {
            const int b  = e >> 4;
            const int j  = e & 15;
            const int jg = jb * 16 + j;
            ooff[n] = (b0 + b) * HH + jg;
            br_[n]  = b_ih[jg] + b_hh[jg];
            bz_[n]  = b_ih[HH + jg] + b_hh[HH + jg];
            bni_[n] = b_ih[2 * HH + jg];
            bnh_[n] = b_hh[2 * HH + jg];
            hp[n]   = hist[ooff[n]];
        }
    }

    CP_WAIT(0);
    __syncthreads();

    float acc[4][4];
    #pragma unroll
    for (int f = 0; f < 4; f++)
        #pragma unroll
        for (int i = 0; i < 4; i++) acc[f][i] = 0.0f;

    float* sG = (float*)(dsm + OFF_A);   // [64][100] gate exchange (aliases A)

    for (int t = 1; t < TT; t++) {
        const __nv_bfloat16* srcH = hh_base + (size_t)((t - 1) & 1) * BB * HH;
        const __nv_bfloat16* srcL = hl_base + (size_t)((t - 1) & 1) * BB * HH;

        // prologue: chunk 0 -> buf 0
        {
            __nv_bfloat16* buf = dsm + OFF_A;
            cp_async16(buf + aDst[0], (aMat[0] ? srcL : srcH) + aSrc[0]);
            cp_async16(buf + aDst[1], (aMat[1] ? srcL : srcH) + aSrc[1]);
            if (a3)
                cp_async16(buf + aDst[2], (aMat[2] ? srcL : srcH) + aSrc[2]);
            CP_COMMIT();
        }

        #pragma unroll 1
        for (int c = 0; c < NCH; c++) {
            if (c + 1 < NCH) {
                __nv_bfloat16* buf = dsm + OFF_A + ((c + 1) & 1) * A_BUF;
                const int k0 = (c + 1) * 64;
                cp_async16(buf + aDst[0], (aMat[0] ? srcL : srcH) + aSrc[0] + k0);
                cp_async16(buf + aDst[1], (aMat[1] ? srcL : srcH) + aSrc[1] + k0);
                if (a3)
                    cp_async16(buf + aDst[2], (aMat[2] ? srcL : srcH) + aSrc[2] + k0);
                CP_COMMIT();
                CP_WAIT(1);
            } else {
                CP_WAIT(0);
            }
            __syncthreads();

            const __nv_bfloat16* bufA = dsm + OFF_A + (c & 1) * A_BUF;
            #pragma unroll
            for (int q = 0; q < 4; q++) {
                uint32_t aH[4], aL[4];
                const int gsA = ((2 * q + a_g0) ^ a_r7) * 8;
                ldsm4(aH, bufA + a_base + gsA);
                ldsm4(aL, bufA + A_MATS + a_base + gsA);
                const int gqB = c * 8 + 2 * q + b_g0;
                #pragma unroll
                for (int p = 0; p < 2; p++) {
                    const int gsB = (gqB & 56) | ((gqB ^ b_r7[p]) & 7);
                    const int off = b_base[p] + gsB * 8;
                    uint32_t bh[4], bl[4];
                    ldsm4(bh, dsm + off);
                    ldsm4(bl, dsm + B_MATS + off);
                    mma_bf16(acc[2 * p],     aH, bh[0], bh[1]);
                    mma_bf16(acc[2 * p],     aH, bl[0], bl[1]);
                    mma_bf16(acc[2 * p],     aL, bh[0], bh[1]);
                    mma_bf16(acc[2 * p + 1], aH, bh[2], bh[3]);
                    mma_bf16(acc[2 * p + 1], aH, bl[2], bl[3]);
                    mma_bf16(acc[2 * p + 1], aL, bh[2], bh[3]);
                }
            }
            __syncthreads();   // buffer consumed (and pre-sG for last chunk)
        }

        // ---- write fragments to sG[64][100] ----
        {
            #pragma unroll
            for (int f = 0; f < 4; f++) {
                const int cb = nv * 32 + f * 8 + (lane & 3) * 2;
                sG[r_base * 100 + cb]           = acc[f][0];
                sG[r_base * 100 + cb + 1]       = acc[f][1];
                sG[(r_base + 8) * 100 + cb]     = acc[f][2];
                sG[(r_base + 8) * 100 + cb + 1] = acc[f][3];
            }
        }
        __syncthreads();

        // ---- gate epilogue (fast MUFU math) ----
        {
            __nv_bfloat16* dstH = hh_base + (size_t)(t & 1) * BB * HH;
            __nv_bfloat16* dstL = hl_base + (size_t)(t & 1) * BB * HH;
            float* hout = hist + (size_t)t * BB * HH;
            #pragma unroll
            for (int n = 0; n < 3; n++) {
                const int e = tid + THR * n;
                if (e < 1024) {
                    const int b = e >> 4, j = e & 15;
                    const float gr = sG[b * 100 + j];
                    const float gz = sG[b * 100 + 16 + j];
                    const float gn = sG[b * 100 + 32 + j];
                    const float hr = sG[b * 100 + 48 + j];
                    const float hz = sG[b * 100 + 64 + j];
                    const float hn = sG[b * 100 + 80 + j];
                    const float rv = fast_sig(gr + hr + br_[n]);
                    const float zv = fast_sig(gz + hz + bz_[n]);
                    const float nn = fast_tanh(gn + bni_[n] + rv * (hn + bnh_[n]));
                    const float hv = (1.0f - zv) * nn + zv * hp[n];
                    hp[n] = hv;
                    hout[ooff[n]] = hv;
                    const __nv_bfloat16 hi = __float2bfloat16(hv);
                    dstH[ooff[n]] = hi;
                    dstL[ooff[n]] = __float2bfloat16(hv - __bfloat162float(hi));
                }
            }
        }

        // reset accumulators
        #pragma unroll
        for (int f = 0; f < 4; f++)
            #pragma unroll
            for (int i = 0; i < 4; i++) acc[f][i] = 0.0f;

        __syncthreads();   // all epilogue stores done (and sG reads done)

        // ---- per-group grid barrier (single-thread release; skip last) ----
        if (t < TT - 1) {
            if (tid == 0) {
                red_release_add(&g_ctrs[bq], 1u);    // publish step t
                const unsigned int target = (unsigned int)t * 32u;
                while (ld_acq(&g_ctrs[bq]) < target) {}
            }
            __syncthreads();
        }
    }
}

// ---------------------------------------------------------------------------
// Generic fp32 GRU step — used only for t = 0 (x = embed row, h = feat).
// ---------------------------------------------------------------------------
__global__ __launch_bounds__(256) void gru_step_kernel(
    const float* __restrict__ x, int xs,
    const float* __restrict__ h,
    const float* __restrict__ w_ih,
    const float* __restrict__ w_hh,
    const float* __restrict__ b_ih,
    const float* __restrict__ b_hh,
    float* __restrict__ h_out)
{
    __shared__ float sX[32][32];
    __shared__ float sH[32][32];
    __shared__ float sWih[3][32][32];
    __shared__ float sWhh[3][32][32];

    const int tid = threadIdx.x;
    const int tj  = tid & 31;
    const int tb  = tid >> 5;
    const int j0  = blockIdx.x * 32;
    const int b0  = blockIdx.y * 32;

    float acc[4][6];
    #pragma unroll
    for (int i = 0; i < 4; i++)
        #pragma unroll
        for (int g = 0; g < 6; g++) acc[i][g] = 0.0f;

    const int lb  = tid >> 3;
    const int lk4 = (tid & 7) * 4;

    for (int k0 = 0; k0 < HH; k0 += 32) {
        float4 xv4 = *(const float4*)(x + (size_t)(b0 + lb) * (size_t)xs + k0 + lk4);
        *(float4*)&sX[lb][lk4] = xv4;
        float4 hv4 = *(const float4*)(h + (size_t)(b0 + lb) * HH + k0 + lk4);
        *(float4*)&sH[lb][lk4] = hv4;
        #pragma unroll
        for (int g = 0; g < 3; g++) {
            float4 wi = *(const float4*)(w_ih + (size_t)(g * HH + j0 + lb) * HH + k0 + lk4);
            sWih[g][lk4 + 0][lb] = wi.x;
            sWih[g][lk4 + 1][lb] = wi.y;
            sWih[g][lk4 + 2][lb] = wi.z;
            sWih[g][lk4 + 3][lb] = wi.w;
            float4 wh = *(const float4*)(w_hh + (size_t)(g * HH + j0 + lb) * HH + k0 + lk4);
            sWhh[g][lk4 + 0][lb] = wh.x;
            sWhh[g][lk4 + 1][lb] = wh.y;
            sWhh[g][lk4 + 2][lb] = wh.z;
            sWhh[g][lk4 + 3][lb] = wh.w;
        }
        __syncthreads();

        #pragma unroll
        for (int kk = 0; kk < 32; kk++) {
            const float wi0 = sWih[0][kk][tj];
            const float wi1 = sWih[1][kk][tj];
            const float wi2 = sWih[2][kk][tj];
            const float wh0 = sWhh[0][kk][tj];
            const float wh1 = sWhh[1][kk][tj];
            const float wh2 = sWhh[2][kk][tj];
            #pragma unroll
            for (int i = 0; i < 4; i++) {
                const float xv = sX[tb * 4 + i][kk];
                const float hv = sH[tb * 4 + i][kk];
                acc[i][0] += xv * wi0;
                acc[i][1] += xv * wi1;
                acc[i][2] += xv * wi2;
                acc[i][3] += hv * wh0;
                acc[i][4] += hv * wh1;
                acc[i][5] += hv * wh2;
            }
        }
        __syncthreads();
    }

    const int j = j0 + tj;
    const float bir  = b_ih[j],          bhr = b_hh[j];
    const float biz  = b_ih[HH + j],     bhz = b_hh[HH + j];
    const float bin_ = b_ih[2 * HH + j], bhn = b_hh[2 * HH + j];
    #pragma unroll
    for (int i = 0; i < 4; i++) {
        const int b = b0 + tb * 4 + i;
        const float r = sigmoidf_(acc[i][0] + bir + acc[i][3] + bhr);
        const float z = sigmoidf_(acc[i][1] + biz + acc[i][4] + bhz);
        const float n = tanhf(acc[i][2] + bin_ + r * (acc[i][5] + bhn));
        const float hp = h[(size_t)b * HH + j];
        h_out[(size_t)b * HH + j] = (1.0f - z) * n + z * hp;
    }
}

// ---------------------------------------------------------------------------
// Projection: out[b][v][t] = hist[t][b][:] . proj_w[v][:] + proj_b[v]
// ---------------------------------------------------------------------------
__global__ __launch_bounds__(512) void proj_kernel(
    const float* __restrict__ proj_w,
    const float* __restrict__ proj_b,
    float* __restrict__ out)
{
    __shared__ float sH[TT][33];
    __shared__ float sW[VV][33];

    const int b   = blockIdx.x;
    const int tid = threadIdx.x;
    const int tg  = tid % 25;
    const int vg  = tid / 25;
    const bool active = (tid < 500);

    float acc[8][5];
    #pragma unroll
    for (int i = 0; i < 8; i++)
        #pragma unroll
        for (int jv = 0; jv < 5; jv++) acc[i][jv] = 0.0f;

    for (int k0 = 0; k0 < HH; k0 += 32) {
        for (int idx = tid; idx < TT * 32; idx += 512) {
            const int t = idx >> 5, k = idx & 31;
            sH[t][k] = g_hist[((size_t)t * BB + b) * HH + k0 + k];
        }
        for (int idx = tid; idx < VV * 32; idx += 512) {
            const int v = idx >> 5, k = idx & 31;
            sW[v][k] = proj_w[(size_t)v * HH + k0 + k];
        }
        __syncthreads();

        if (active) {
            #pragma unroll
            for (int kk = 0; kk < 32; kk++) {
                float wv[5];
                #pragma unroll
                for (int jv = 0; jv < 5; jv++) wv[jv] = sW[vg * 5 + jv][kk];
                #pragma unroll
                for (int i = 0; i < 8; i++) {
                    const float hv = sH[tg + 25 * i][kk];
                    #pragma unroll
                    for (int jv = 0; jv < 5; jv++) acc[i][jv] += hv * wv[jv];
                }
            }
        }
        __syncthreads();
    }

    if (active) {
        float pb[5];
        #pragma unroll
        for (int jv = 0; jv < 5; jv++) pb[jv] = proj_b[vg * 5 + jv];
        #pragma unroll
        for (int i = 0; i < 8; i++) {
            const int t = tg + 25 * i;
            #pragma unroll
            for (int jv = 0; jv < 5; jv++) {
                const int v = vg * 5 + jv;
                out[((size_t)b * VV + v) * TT + t] = acc[i][jv] + pb[jv];
            }
        }
    }
}

// ---------------------------------------------------------------------------
extern "C" void kernel_launch(void* const* d_in, const int* in_sizes, int n_in,
                              void* d_out, int out_size)
{
    (void)in_sizes; (void)n_in; (void)out_size;
    const float* feat   = (const float*)d_in[0];
    const float* embed  = (const float*)d_in[1];
    const float* w_ih   = (const float*)d_in[2];
    const float* w_hh   = (const float*)d_in[3];
    const float* b_ih   = (const float*)d_in[4];
    const float* b_hh   = (const float*)d_in[5];
    const float* proj_w = (const float*)d_in[6];
    const float* proj_b = (const float*)d_in[7];
    float* out = (float*)d_out;

    float* hist = nullptr;
    cudaGetSymbolAddress((void**)&hist, g_hist);
    __nv_bfloat16* hhp = nullptr;
    cudaGetSymbolAddress((void**)&hhp, g_hh);
    __nv_bfloat16* hlp = nullptr;
    cudaGetSymbolAddress((void**)&hlp, g_hl);

    cudaFuncSetAttribute(gru_persistent,
                         cudaFuncAttributeMaxDynamicSharedMemorySize, SMEM_P);

    prep_weights<<<(6 * HH * HH + 255) / 256, 256>>>(w_ih, w_hh);
    reset_ctr_kernel<<<1, 32>>>();

    // step 0: x = embed[SOS=0] broadcast, h = feat  -> hist[0]
    gru_step_kernel<<<dim3(HH / 32, BB / 32), 256>>>(embed, 0, feat,
                                                     w_ih, w_hh, b_ih, b_hh, hist);
    convert_h<<<(BB * HH + 255) / 256, 256>>>(hist, hhp, hlp);   // -> pp slot 0

    // steps 1..199: persistent tensor-core kernel (one wave of 128 blocks)
    gru_persistent<<<dim3(32, 4), THR, SMEM_P>>>(b_ih, b_hh, hist, hhp, hlp);

    proj_kernel<<<BB, 512>>>(proj_w, proj_b, out);
}